// round 1
// baseline (speedup 1.0000x reference)
#include <cuda_runtime.h>
#include <math.h>

#define T_TOK 4096
#define DM    1024
#define NE    16
#define CAP   1024
#define DFF   512
#define DFS   1024

// ---------------- scratch (static device globals; no allocation) ----------------
__device__ int   g_cnt[NE];
__device__ int   g_slot[T_TOK * 2];     // slot = e*CAP+pos, or -1 if dropped
__device__ float g_wt[T_TOK * 2];       // renormalized top-2 weights
__device__ float g_X [(size_t)NE * CAP * DM];   // gathered tokens per expert
__device__ float g_H [(size_t)NE * CAP * DFF];  // expert hidden (silu(xw1)*xw3)
__device__ float g_Y [(size_t)NE * CAP * DM];   // expert outputs
__device__ float g_Hs[(size_t)T_TOK * DFS];     // shared-expert hidden

// ---------------- counters reset (graph-replay determinism) ----------------
__global__ void zero_cnt_kernel() {
    if (threadIdx.x < NE) g_cnt[threadIdx.x] = 0;
}

// ---------------- router: logits -> softmax -> top2 -> slots + fused gather ----------------
// one warp per token; 8 tokens per block; Wg staged in smem in 2 chunks of 512 d-rows
__global__ void router_kernel(const float* __restrict__ hs, const float* __restrict__ Wg) {
    __shared__ float sW[NE * 513];           // [e][513] padded, chunk of 512 d
    const int tid  = threadIdx.x;
    const int lane = tid & 31;
    const int wid  = tid >> 5;
    const int t    = blockIdx.x * 8 + wid;

    // load token row into registers (coalesced)
    float hreg[32];
#pragma unroll
    for (int j = 0; j < 32; j++) hreg[j] = hs[(size_t)t * DM + j * 32 + lane];

    float plog[NE];
#pragma unroll
    for (int e = 0; e < NE; e++) plog[e] = 0.f;

    for (int c = 0; c < 2; c++) {
        __syncthreads();
        // stage Wg chunk transposed: sW[e*513 + d_local] = Wg[(c*512+d_local)*16 + e]
        for (int i = tid; i < 512 * NE; i += 256) {
            int d = i >> 4, e = i & 15;
            sW[e * 513 + d] = Wg[(size_t)c * 8192 + i];
        }
        __syncthreads();
#pragma unroll
        for (int e = 0; e < NE; e++) {
            float s = 0.f;
#pragma unroll
            for (int j = 0; j < 16; j++)
                s += hreg[c * 16 + j] * sW[e * 513 + j * 32 + lane];
            plog[e] += s;
        }
    }
    // warp-reduce each logit (all lanes get full value)
#pragma unroll
    for (int e = 0; e < NE; e++) {
        float v = plog[e];
#pragma unroll
        for (int o = 16; o > 0; o >>= 1) v += __shfl_xor_sync(0xffffffffu, v, o);
        plog[e] = v;
    }
    // softmax (fp32)
    float mx = plog[0];
#pragma unroll
    for (int e = 1; e < NE; e++) mx = fmaxf(mx, plog[e]);
    float sum = 0.f;
#pragma unroll
    for (int e = 0; e < NE; e++) { plog[e] = expf(plog[e] - mx); sum += plog[e]; }
    // top-2 (ties -> lowest index, matching lax.top_k)
    int e0 = 0; float p0 = plog[0];
#pragma unroll
    for (int e = 1; e < NE; e++) if (plog[e] > p0) { p0 = plog[e]; e0 = e; }
    int e1 = 0; float p1 = -1.f;
#pragma unroll
    for (int e = 0; e < NE; e++) if (e != e0 && plog[e] > p1) { p1 = plog[e]; e1 = e; }
    const float rnorm = 1.f / (p0 + p1);
    const float w0 = p0 * rnorm, w1 = p1 * rnorm;   // (softmax denom cancels)

    // slot assignment (lane 0) + broadcast
    int s0 = 0, s1 = 0;
    if (lane == 0) {
        int pos = atomicAdd(&g_cnt[e0], 1);
        s0 = (pos < CAP) ? e0 * CAP + pos : -1;
        pos = atomicAdd(&g_cnt[e1], 1);
        s1 = (pos < CAP) ? e1 * CAP + pos : -1;
        g_slot[t * 2]     = s0;  g_slot[t * 2 + 1] = s1;
        g_wt[t * 2]       = w0;  g_wt[t * 2 + 1]   = w1;
    }
    s0 = __shfl_sync(0xffffffffu, s0, 0);
    s1 = __shfl_sync(0xffffffffu, s1, 0);

    // fused gather: warp already holds the row
    if (s0 >= 0) {
#pragma unroll
        for (int j = 0; j < 32; j++) g_X[(size_t)s0 * DM + j * 32 + lane] = hreg[j];
    }
    if (s1 >= 0) {
#pragma unroll
        for (int j = 0; j < 32; j++) g_X[(size_t)s1 * DM + j * 32 + lane] = hreg[j];
    }
}

// ---------------- fused SwiGLU GEMM: H = silu(X@W1) * (X@W3) ----------------
// MODE 0: expert path (X=g_X[e], W per expert, H=g_H[e], rows limited by g_cnt[e])
// MODE 1: shared path (X=hs,     W=ws1/ws3,    H=g_Hs,   all T_TOK rows)
template <int MODE>
__global__ void swiglu_gemm_k(const float* __restrict__ Xext,
                              const float* __restrict__ W1e,
                              const float* __restrict__ W3e) {
    constexpr int N = (MODE == 0) ? DFF : DFS;

    const int e = blockIdx.z;
    int valid;
    const float *X, *W1, *W3;
    float* H;
    if (MODE == 0) {
        valid = min(g_cnt[e], CAP);
        X  = g_X + (size_t)e * CAP * DM;
        W1 = W1e + (size_t)e * DM * DFF;
        W3 = W3e + (size_t)e * DM * DFF;
        H  = g_H + (size_t)e * CAP * DFF;
    } else {
        valid = T_TOK;
        X = Xext; W1 = W1e; W3 = W3e; H = g_Hs;
    }
    const int row0 = blockIdx.y * 64;
    if (row0 >= valid) return;
    const int col0 = blockIdx.x * 64;

    __shared__ float As[16][65];
    __shared__ float B1[16][64];
    __shared__ float B3[16][64];

    const int tid  = threadIdx.x;
    const int arow = tid >> 2, aq = tid & 3;
    const int bk   = tid >> 4, bq = tid & 15;
    const int tx   = tid & 15, ty = tid >> 4;

    float acc1[4][4] = {}, acc3[4][4] = {};

    for (int k0 = 0; k0 < DM; k0 += 16) {
        float4 av = make_float4(0.f, 0.f, 0.f, 0.f);
        if (row0 + arow < valid)
            av = *(const float4*)&X[(size_t)(row0 + arow) * DM + k0 + aq * 4];
        float4 bv1 = *(const float4*)&W1[(size_t)(k0 + bk) * N + col0 + bq * 4];
        float4 bv3 = *(const float4*)&W3[(size_t)(k0 + bk) * N + col0 + bq * 4];
        __syncthreads();
        As[aq * 4 + 0][arow] = av.x; As[aq * 4 + 1][arow] = av.y;
        As[aq * 4 + 2][arow] = av.z; As[aq * 4 + 3][arow] = av.w;
        *(float4*)&B1[bk][bq * 4] = bv1;
        *(float4*)&B3[bk][bq * 4] = bv3;
        __syncthreads();
#pragma unroll
        for (int kk = 0; kk < 16; kk++) {
            float a[4];
#pragma unroll
            for (int i = 0; i < 4; i++) a[i] = As[kk][ty * 4 + i];
            float4 f1 = *(float4*)&B1[kk][tx * 4];
            float4 f3 = *(float4*)&B3[kk][tx * 4];
            float b1a[4] = { f1.x, f1.y, f1.z, f1.w };
            float b3a[4] = { f3.x, f3.y, f3.z, f3.w };
#pragma unroll
            for (int i = 0; i < 4; i++)
#pragma unroll
                for (int j = 0; j < 4; j++) {
                    acc1[i][j] += a[i] * b1a[j];
                    acc3[i][j] += a[i] * b3a[j];
                }
        }
    }
#pragma unroll
    for (int i = 0; i < 4; i++) {
        const int r = row0 + ty * 4 + i;
        if (r >= valid) continue;
        float4 o;
        float* op = (float*)&o;
#pragma unroll
        for (int j = 0; j < 4; j++) {
            float x1 = acc1[i][j];
            float sv = x1 / (1.f + __expf(-x1));
            op[j] = sv * acc3[i][j];
        }
        *(float4*)&H[(size_t)r * N + col0 + tx * 4] = o;
    }
}

// ---------------- plain GEMM: O = A @ W ----------------
// MODE 0: expert down-proj (A=g_H[e], W=w2[e], O=g_Y[e], K=DFF)
// MODE 1: shared down-proj (A=g_Hs,   W=ws2,   O=d_out,  K=DFS) -- writes whole output
template <int MODE>
__global__ void plain_gemm_k(const float* __restrict__ We,
                             float* __restrict__ Oext) {
    constexpr int N  = DM;
    constexpr int Kd = (MODE == 0) ? DFF : DFS;

    const int e = blockIdx.z;
    int valid;
    const float *A, *W;
    float* O;
    if (MODE == 0) {
        valid = min(g_cnt[e], CAP);
        A = g_H + (size_t)e * CAP * DFF;
        W = We  + (size_t)e * DFF * DM;
        O = g_Y + (size_t)e * CAP * DM;
    } else {
        valid = T_TOK;
        A = g_Hs; W = We; O = Oext;
    }
    const int row0 = blockIdx.y * 64;
    if (row0 >= valid) return;
    const int col0 = blockIdx.x * 64;

    __shared__ float As[16][65];
    __shared__ float Bs[16][64];

    const int tid  = threadIdx.x;
    const int arow = tid >> 2, aq = tid & 3;
    const int bk   = tid >> 4, bq = tid & 15;
    const int tx   = tid & 15, ty = tid >> 4;

    float acc[4][4] = {};

    for (int k0 = 0; k0 < Kd; k0 += 16) {
        float4 av = make_float4(0.f, 0.f, 0.f, 0.f);
        if (row0 + arow < valid)
            av = *(const float4*)&A[(size_t)(row0 + arow) * Kd + k0 + aq * 4];
        float4 bv = *(const float4*)&W[(size_t)(k0 + bk) * N + col0 + bq * 4];
        __syncthreads();
        As[aq * 4 + 0][arow] = av.x; As[aq * 4 + 1][arow] = av.y;
        As[aq * 4 + 2][arow] = av.z; As[aq * 4 + 3][arow] = av.w;
        *(float4*)&Bs[bk][bq * 4] = bv;
        __syncthreads();
#pragma unroll
        for (int kk = 0; kk < 16; kk++) {
            float a[4];
#pragma unroll
            for (int i = 0; i < 4; i++) a[i] = As[kk][ty * 4 + i];
            float4 fb = *(float4*)&Bs[kk][tx * 4];
            float ba[4] = { fb.x, fb.y, fb.z, fb.w };
#pragma unroll
            for (int i = 0; i < 4; i++)
#pragma unroll
                for (int j = 0; j < 4; j++) acc[i][j] += a[i] * ba[j];
        }
    }
#pragma unroll
    for (int i = 0; i < 4; i++) {
        const int r = row0 + ty * 4 + i;
        if (r >= valid) continue;
        float4 o = make_float4(acc[i][0], acc[i][1], acc[i][2], acc[i][3]);
        *(float4*)&O[(size_t)r * N + col0 + tx * 4] = o;
    }
}

// ---------------- combine: out[t] += w0*Y[s0] + w1*Y[s1] ----------------
__global__ void combine_kernel(float* __restrict__ out) {
    const int t  = blockIdx.x;
    const int s0 = g_slot[2 * t], s1 = g_slot[2 * t + 1];
    const float w0 = g_wt[2 * t], w1 = g_wt[2 * t + 1];
    for (int i = threadIdx.x; i < DM; i += 256) {
        float v = out[(size_t)t * DM + i];
        if (s0 >= 0) v += w0 * g_Y[(size_t)s0 * DM + i];
        if (s1 >= 0) v += w1 * g_Y[(size_t)s1 * DM + i];
        out[(size_t)t * DM + i] = v;
    }
}

// ---------------- launch ----------------
extern "C" void kernel_launch(void* const* d_in, const int* in_sizes, int n_in,
                              void* d_out, int out_size) {
    const float* hs  = (const float*)d_in[0];
    const float* Wg  = (const float*)d_in[1];
    const float* w1  = (const float*)d_in[2];
    const float* w3  = (const float*)d_in[3];
    const float* w2  = (const float*)d_in[4];
    const float* ws1 = (const float*)d_in[5];
    const float* ws3 = (const float*)d_in[6];
    const float* ws2 = (const float*)d_in[7];
    float* out = (float*)d_out;

    zero_cnt_kernel<<<1, 32>>>();
    router_kernel<<<T_TOK / 8, 256>>>(hs, Wg);

    // expert path
    swiglu_gemm_k<0><<<dim3(DFF / 64, CAP / 64, NE), 256>>>(nullptr, w1, w3);
    plain_gemm_k<0><<<dim3(DM / 64, CAP / 64, NE), 256>>>(w2, nullptr);

    // shared expert path (second GEMM writes the full output -> clears poison)
    swiglu_gemm_k<1><<<dim3(DFS / 64, T_TOK / 64, 1), 256>>>(hs, ws1, ws3);
    plain_gemm_k<1><<<dim3(DM / 64, T_TOK / 64, 1), 256>>>(ws2, out);

    // add routed-expert contributions
    combine_kernel<<<T_TOK, 256>>>(out);
}

// round 3
// speedup vs baseline: 1.5699x; 1.5699x over previous
#include <cuda_runtime.h>
#include <cuda_bf16.h>
#include <cstdint>
#include <math.h>

#define T_TOK 4096
#define DM    1024
#define NE    16
#define CAP   1024
#define DFF   512
#define DFS   1024

// ---------------- scratch (static device globals; no allocation) ----------------
__device__ int   g_cnt[NE];
__device__ int   g_slot[T_TOK * 2];
__device__ float g_wt[T_TOK * 2];
__device__ float g_X [(size_t)NE * CAP * DM];
__device__ float g_H [(size_t)NE * CAP * DFF];
__device__ float g_Y [(size_t)NE * CAP * DM];
__device__ float g_Hs[(size_t)T_TOK * DFS];

// bf16 hi/lo split weights, transposed to [N, K] per expert
__device__ __nv_bfloat16 g_w1h[(size_t)NE * DFF * DM], g_w1l[(size_t)NE * DFF * DM];
__device__ __nv_bfloat16 g_w3h[(size_t)NE * DFF * DM], g_w3l[(size_t)NE * DFF * DM];
__device__ __nv_bfloat16 g_w2h[(size_t)NE * DM * DFF], g_w2l[(size_t)NE * DM * DFF];
__device__ __nv_bfloat16 g_ws1h[(size_t)DFS * DM], g_ws1l[(size_t)DFS * DM];
__device__ __nv_bfloat16 g_ws3h[(size_t)DFS * DM], g_ws3l[(size_t)DFS * DM];
__device__ __nv_bfloat16 g_ws2h[(size_t)DM * DFS], g_ws2l[(size_t)DM * DFS];

// ---------------- helpers ----------------
__device__ __forceinline__ uint32_t smem_u32(const void* p) {
    uint32_t r;
    asm("{ .reg .u64 t; cvta.to.shared.u64 t, %1; cvt.u32.u64 %0, t; }" : "=r"(r) : "l"(p));
    return r;
}

#define STS128(addr, a, b, c, d) \
    asm volatile("st.shared.v4.b32 [%0], {%1,%2,%3,%4};" :: "r"(addr), "r"(a), "r"(b), "r"(c), "r"(d) : "memory")

#define LDSM_X4(r0, r1, r2, r3, addr) \
    asm volatile("ldmatrix.sync.aligned.m8n8.x4.shared.b16 {%0,%1,%2,%3}, [%4];" \
                 : "=r"(r0), "=r"(r1), "=r"(r2), "=r"(r3) : "r"(addr))

__device__ __forceinline__ void mma_bf16(float* c, const uint32_t* a, const uint32_t* b) {
    asm volatile("mma.sync.aligned.m16n8k16.row.col.f32.bf16.bf16.f32 "
                 "{%0,%1,%2,%3}, {%4,%5,%6,%7}, {%8,%9}, {%0,%1,%2,%3};"
                 : "+f"(c[0]), "+f"(c[1]), "+f"(c[2]), "+f"(c[3])
                 : "r"(a[0]), "r"(a[1]), "r"(a[2]), "r"(a[3]), "r"(b[0]), "r"(b[1]));
}

// swizzled smem address: 128B rows of 8x16B chunks, chunk ^= (row & 7)
__device__ __forceinline__ uint32_t swz(uint32_t base, int r, int byteoff) {
    return base + (uint32_t)(r * 128) + (uint32_t)(((((byteoff >> 4) ^ (r & 7)) << 4)) | (byteoff & 15));
}

// fp32 -> (bf16 hi, bf16 lo) packed pairs
__device__ __forceinline__ void split2(float a, float b, uint32_t& h, uint32_t& l) {
    __nv_bfloat162 H = __floats2bfloat162_rn(a, b);
    float2 Hf = __bfloat1622float2(H);
    __nv_bfloat162 L = __floats2bfloat162_rn(a - Hf.x, b - Hf.y);
    __builtin_memcpy(&h, &H, 4);
    __builtin_memcpy(&l, &L, 4);
}

// stage A (128 rows x 64 k) fp32 -> hi/lo bf16 smem (swizzled); 256 threads
__device__ __forceinline__ void load_A_tile(const float* __restrict__ src, int ldk,
                                            uint32_t sAh, uint32_t sAl) {
    const int tid = threadIdx.x;
    const int r = tid >> 1, seg = tid & 1;
    const float4* p = reinterpret_cast<const float4*>(src + (size_t)r * ldk + seg * 32);
#pragma unroll
    for (int i = 0; i < 4; i++) {
        float4 f0 = p[2 * i], f1 = p[2 * i + 1];
        uint32_t h0, l0, h1, l1, h2, l2, h3, l3;
        split2(f0.x, f0.y, h0, l0);
        split2(f0.z, f0.w, h1, l1);
        split2(f1.x, f1.y, h2, l2);
        split2(f1.z, f1.w, h3, l3);
        const int c = seg * 4 + i;
        const uint32_t off = (uint32_t)(r * 128 + ((c ^ (r & 7)) << 4));
        STS128(sAh + off, h0, h1, h2, h3);
        STS128(sAl + off, l0, l1, l2, l3);
    }
}

// stage B (rows x 64 k) bf16 hi/lo -> swizzled smem; 2 thread-slots per row
__device__ __forceinline__ void copy_B_tile(const __nv_bfloat16* __restrict__ sh,
                                            const __nv_bfloat16* __restrict__ sl,
                                            int ldk, uint32_t dh, uint32_t dl, int lt) {
    const int r = lt >> 1, seg = lt & 1;
#pragma unroll
    for (int i = 0; i < 4; i++) {
        const int c = seg * 4 + i;
        uint4 vh = *reinterpret_cast<const uint4*>(sh + (size_t)r * ldk + c * 8);
        uint4 vl = *reinterpret_cast<const uint4*>(sl + (size_t)r * ldk + c * 8);
        const uint32_t off = (uint32_t)(r * 128 + ((c ^ (r & 7)) << 4));
        STS128(dh + off, vh.x, vh.y, vh.z, vh.w);
        STS128(dl + off, vl.x, vl.y, vl.z, vl.w);
    }
}

#define SMEM_BYTES (65536 + 1024)

// ---------------- weight transpose + bf16 split prepass ----------------
template <int ID>
__global__ void wsplit_kernel(const float* __restrict__ W, int K, int N) {
    __nv_bfloat16 *oh, *ol;
    if (ID == 0) { oh = g_w1h;  ol = g_w1l;  }
    if (ID == 1) { oh = g_w3h;  ol = g_w3l;  }
    if (ID == 2) { oh = g_w2h;  ol = g_w2l;  }
    if (ID == 3) { oh = g_ws1h; ol = g_ws1l; }
    if (ID == 4) { oh = g_ws3h; ol = g_ws3l; }
    if (ID == 5) { oh = g_ws2h; ol = g_ws2l; }
    const size_t eoff = (size_t)blockIdx.z * K * N;
    W += eoff; oh += eoff; ol += eoff;

    __shared__ float t[32][33];
    const int kb = blockIdx.y * 32, nb = blockIdx.x * 32;
    const int tx = threadIdx.x, ty = threadIdx.y;
#pragma unroll
    for (int i = 0; i < 4; i++)
        t[ty + 8 * i][tx] = W[(size_t)(kb + ty + 8 * i) * N + nb + tx];
    __syncthreads();
#pragma unroll
    for (int i = 0; i < 4; i++) {
        const int n = nb + ty + 8 * i;
        float v = t[tx][ty + 8 * i];
        __nv_bfloat16 hi = __float2bfloat16(v);
        __nv_bfloat16 lo = __float2bfloat16(v - __bfloat162float(hi));
        oh[(size_t)n * K + kb + tx] = hi;
        ol[(size_t)n * K + kb + tx] = lo;
    }
}

// ---------------- counters reset ----------------
__global__ void zero_cnt_kernel() {
    if (threadIdx.x < NE) g_cnt[threadIdx.x] = 0;
}

// ---------------- router (verified in R1) ----------------
__global__ void router_kernel(const float* __restrict__ hs, const float* __restrict__ Wg) {
    __shared__ float sW[NE * 513];
    const int tid = threadIdx.x, lane = tid & 31, wid = tid >> 5;
    const int t = blockIdx.x * 8 + wid;

    float hreg[32];
#pragma unroll
    for (int j = 0; j < 32; j++) hreg[j] = hs[(size_t)t * DM + j * 32 + lane];

    float plog[NE];
#pragma unroll
    for (int e = 0; e < NE; e++) plog[e] = 0.f;

    for (int c = 0; c < 2; c++) {
        __syncthreads();
        for (int i = tid; i < 512 * NE; i += 256) {
            int d = i >> 4, e = i & 15;
            sW[e * 513 + d] = Wg[(size_t)c * 8192 + i];
        }
        __syncthreads();
#pragma unroll
        for (int e = 0; e < NE; e++) {
            float s = 0.f;
#pragma unroll
            for (int j = 0; j < 16; j++)
                s += hreg[c * 16 + j] * sW[e * 513 + j * 32 + lane];
            plog[e] += s;
        }
    }
#pragma unroll
    for (int e = 0; e < NE; e++) {
        float v = plog[e];
#pragma unroll
        for (int o = 16; o > 0; o >>= 1) v += __shfl_xor_sync(0xffffffffu, v, o);
        plog[e] = v;
    }
    float mx = plog[0];
#pragma unroll
    for (int e = 1; e < NE; e++) mx = fmaxf(mx, plog[e]);
#pragma unroll
    for (int e = 0; e < NE; e++) plog[e] = expf(plog[e] - mx);
    int e0 = 0; float p0 = plog[0];
#pragma unroll
    for (int e = 1; e < NE; e++) if (plog[e] > p0) { p0 = plog[e]; e0 = e; }
    int e1 = 0; float p1 = -1.f;
#pragma unroll
    for (int e = 0; e < NE; e++) if (e != e0 && plog[e] > p1) { p1 = plog[e]; e1 = e; }
    const float rnorm = 1.f / (p0 + p1);
    const float w0 = p0 * rnorm, w1 = p1 * rnorm;

    int s0 = 0, s1 = 0;
    if (lane == 0) {
        int pos = atomicAdd(&g_cnt[e0], 1);
        s0 = (pos < CAP) ? e0 * CAP + pos : -1;
        pos = atomicAdd(&g_cnt[e1], 1);
        s1 = (pos < CAP) ? e1 * CAP + pos : -1;
        g_slot[t * 2] = s0; g_slot[t * 2 + 1] = s1;
        g_wt[t * 2] = w0;   g_wt[t * 2 + 1] = w1;
    }
    s0 = __shfl_sync(0xffffffffu, s0, 0);
    s1 = __shfl_sync(0xffffffffu, s1, 0);
    if (s0 >= 0) {
#pragma unroll
        for (int j = 0; j < 32; j++) g_X[(size_t)s0 * DM + j * 32 + lane] = hreg[j];
    }
    if (s1 >= 0) {
#pragma unroll
        for (int j = 0; j < 32; j++) g_X[(size_t)s1 * DM + j * 32 + lane] = hreg[j];
    }
}

// ======================= HMMA GEMM kernels (3-term bf16 split) =======================
// block tile 128x128, warp grid 4(m) x 2(n), warp tile 32x64, K-chunk 64, single buffer.

// loads A fragments for both m-tiles of this warp at k16-index kk
__device__ __forceinline__ void ld_a_frags(uint32_t sA, int m0, int lane, int kk, uint32_t a[2][4]) {
    const int r = m0 + (lane & 15);
    const int byte = kk * 32 + ((lane >> 4) << 4);
    LDSM_X4(a[0][0], a[0][1], a[0][2], a[0][3], swz(sA, r, byte));
    LDSM_X4(a[1][0], a[1][1], a[1][2], a[1][3], swz(sA, r + 16, byte));
}

// loads B fragments for one pair of n8 tiles at row base nb
__device__ __forceinline__ void ld_b_pair(uint32_t sB, int nb, int lane, int kk, uint32_t b[4]) {
    const int r = nb + ((lane >> 4) << 3) + (lane & 7);
    const int byte = kk * 32 + (((lane >> 3) & 1) << 4);
    LDSM_X4(b[0], b[1], b[2], b[3], swz(sB, r, byte));
}

__device__ __forceinline__ float silu_f(float x) {
    return x / (1.f + __expf(-x));
}

// ---------------- SwiGLU: H = silu(A@W1) * (A@W3); B tile = [64 W1 cols | 64 W3 cols] ----------------
template <int MODE>
__global__ __launch_bounds__(256, 1) void swiglu_tc(const float* __restrict__ Xext) {
    constexpr int KT = DM;
    constexpr int NS = KT / 64;
    constexpr int NTOT = (MODE == 0) ? DFF : DFS;

    const int e = blockIdx.z;
    const float* A;
    const __nv_bfloat16 *B1h, *B1l, *B3h, *B3l;
    float* H;
    int valid;
    if (MODE == 0) {
        valid = min(g_cnt[e], CAP);
        A   = g_X + (size_t)e * CAP * DM;
        B1h = g_w1h + (size_t)e * DFF * DM;  B1l = g_w1l + (size_t)e * DFF * DM;
        B3h = g_w3h + (size_t)e * DFF * DM;  B3l = g_w3l + (size_t)e * DFF * DM;
        H   = g_H + (size_t)e * CAP * DFF;
    } else {
        valid = T_TOK;
        A = Xext;
        B1h = g_ws1h; B1l = g_ws1l; B3h = g_ws3h; B3l = g_ws3l;
        H = g_Hs;
    }
    const int row0 = blockIdx.y * 128;
    if (row0 >= valid) return;
    const int col0 = blockIdx.x * 64;          // 64 SwiGLU output columns per block

    extern __shared__ char smem[];
    const uint32_t sb = (smem_u32(smem) + 1023u) & ~1023u;
    const uint32_t sAh = sb, sAl = sb + 16384;
    const uint32_t sBh = sb + 32768, sBl = sb + 49152;

    const int tid = threadIdx.x, lane = tid & 31, warp = tid >> 5;
    const int warpM = warp & 3, warpN = warp >> 2;
    const int m0 = warpM * 32;

    float acc[2][8][4];
#pragma unroll
    for (int i = 0; i < 2; i++)
#pragma unroll
        for (int j = 0; j < 8; j++)
#pragma unroll
            for (int q = 0; q < 4; q++) acc[i][j][q] = 0.f;

    for (int s = 0; s < NS; s++) {
        const int k0 = s * 64;
        __syncthreads();
        load_A_tile(A + (size_t)row0 * KT + k0, KT, sAh, sAl);
        if (tid < 128)
            copy_B_tile(B1h + (size_t)col0 * KT + k0, B1l + (size_t)col0 * KT + k0,
                        KT, sBh, sBl, tid);
        else
            copy_B_tile(B3h + (size_t)col0 * KT + k0, B3l + (size_t)col0 * KT + k0,
                        KT, sBh + 64 * 128, sBl + 64 * 128, tid - 128);
        __syncthreads();
#pragma unroll
        for (int kk = 0; kk < 4; kk++) {
            uint32_t ah[2][4], al[2][4], bh[4][4], bl[4][4];
            ld_a_frags(sAh, m0, lane, kk, ah);
            ld_a_frags(sAl, m0, lane, kk, al);
            // pairs 0,1: W1 half rows [warpN*32 .. +32); pairs 2,3: W3 half at +64
#pragma unroll
            for (int p = 0; p < 4; p++) {
                const int nb = (p < 2) ? (warpN * 32 + p * 16) : (64 + warpN * 32 + (p - 2) * 16);
                ld_b_pair(sBh, nb, lane, kk, bh[p]);
                ld_b_pair(sBl, nb, lane, kk, bl[p]);
            }
#pragma unroll
            for (int mt = 0; mt < 2; mt++)
#pragma unroll
                for (int nt = 0; nt < 8; nt++) {
                    const uint32_t* ph = &bh[nt >> 1][(nt & 1) * 2];
                    const uint32_t* pl = &bl[nt >> 1][(nt & 1) * 2];
                    mma_bf16(acc[mt][nt], ah[mt], ph);
                    mma_bf16(acc[mt][nt], ah[mt], pl);
                    mma_bf16(acc[mt][nt], al[mt], ph);
                }
        }
    }

    // epilogue: nt 0..3 -> W1 (acc1), nt 4..7 -> W3 (acc3), same output column
#pragma unroll
    for (int mt = 0; mt < 2; mt++) {
        const int rbase = row0 + m0 + mt * 16 + (lane >> 2);
#pragma unroll
        for (int nt = 0; nt < 4; nt++) {
            const int col = col0 + warpN * 32 + nt * 8 + (lane & 3) * 2;
            float* c1 = acc[mt][nt];
            float* c3 = acc[mt][nt + 4];
            float2 o0 = make_float2(silu_f(c1[0]) * c3[0], silu_f(c1[1]) * c3[1]);
            float2 o1 = make_float2(silu_f(c1[2]) * c3[2], silu_f(c1[3]) * c3[3]);
            *reinterpret_cast<float2*>(H + (size_t)rbase * NTOT + col) = o0;
            *reinterpret_cast<float2*>(H + (size_t)(rbase + 8) * NTOT + col) = o1;
        }
    }
}

// ---------------- plain GEMM: O = A @ W ----------------
template <int MODE>
__global__ __launch_bounds__(256, 1) void plain_tc(float* __restrict__ Oext) {
    constexpr int KT = (MODE == 0) ? DFF : DFS;
    constexpr int NS = KT / 64;

    const int e = blockIdx.z;
    const float* A;
    const __nv_bfloat16 *Bh, *Bl;
    float* O;
    int valid;
    if (MODE == 0) {
        valid = min(g_cnt[e], CAP);
        A  = g_H + (size_t)e * CAP * DFF;
        Bh = g_w2h + (size_t)e * DM * DFF;
        Bl = g_w2l + (size_t)e * DM * DFF;
        O  = g_Y + (size_t)e * CAP * DM;
    } else {
        valid = T_TOK;
        A = g_Hs; Bh = g_ws2h; Bl = g_ws2l; O = Oext;
    }
    const int row0 = blockIdx.y * 128;
    if (row0 >= valid) return;
    const int col0 = blockIdx.x * 128;

    extern __shared__ char smem[];
    const uint32_t sb = (smem_u32(smem) + 1023u) & ~1023u;
    const uint32_t sAh = sb, sAl = sb + 16384;
    const uint32_t sBh = sb + 32768, sBl = sb + 49152;

    const int tid = threadIdx.x, lane = tid & 31, warp = tid >> 5;
    const int warpM = warp & 3, warpN = warp >> 2;
    const int m0 = warpM * 32;

    float acc[2][8][4];
#pragma unroll
    for (int i = 0; i < 2; i++)
#pragma unroll
        for (int j = 0; j < 8; j++)
#pragma unroll
            for (int q = 0; q < 4; q++) acc[i][j][q] = 0.f;

    for (int s = 0; s < NS; s++) {
        const int k0 = s * 64;
        __syncthreads();
        load_A_tile(A + (size_t)row0 * KT + k0, KT, sAh, sAl);
        copy_B_tile(Bh + (size_t)col0 * KT + k0, Bl + (size_t)col0 * KT + k0, KT, sBh, sBl, tid);
        __syncthreads();
#pragma unroll
        for (int kk = 0; kk < 4; kk++) {
            uint32_t ah[2][4], al[2][4], bh[4][4], bl[4][4];
            ld_a_frags(sAh, m0, lane, kk, ah);
            ld_a_frags(sAl, m0, lane, kk, al);
#pragma unroll
            for (int p = 0; p < 4; p++) {
                const int nb = warpN * 64 + p * 16;
                ld_b_pair(sBh, nb, lane, kk, bh[p]);
                ld_b_pair(sBl, nb, lane, kk, bl[p]);
            }
#pragma unroll
            for (int mt = 0; mt < 2; mt++)
#pragma unroll
                for (int nt = 0; nt < 8; nt++) {
                    const uint32_t* ph = &bh[nt >> 1][(nt & 1) * 2];
                    const uint32_t* pl = &bl[nt >> 1][(nt & 1) * 2];
                    mma_bf16(acc[mt][nt], ah[mt], ph);
                    mma_bf16(acc[mt][nt], ah[mt], pl);
                    mma_bf16(acc[mt][nt], al[mt], ph);
                }
        }
    }

#pragma unroll
    for (int mt = 0; mt < 2; mt++) {
        const int rbase = row0 + m0 + mt * 16 + (lane >> 2);
#pragma unroll
        for (int nt = 0; nt < 8; nt++) {
            const int col = col0 + warpN * 64 + nt * 8 + (lane & 3) * 2;
            float* c = acc[mt][nt];
            *reinterpret_cast<float2*>(O + (size_t)rbase * DM + col) = make_float2(c[0], c[1]);
            *reinterpret_cast<float2*>(O + (size_t)(rbase + 8) * DM + col) = make_float2(c[2], c[3]);
        }
    }
}

// ---------------- combine ----------------
__global__ void combine_kernel(float* __restrict__ out) {
    const int t = blockIdx.x;
    const int s0 = g_slot[2 * t], s1 = g_slot[2 * t + 1];
    const float w0 = g_wt[2 * t], w1 = g_wt[2 * t + 1];
    for (int i = threadIdx.x; i < DM; i += 256) {
        float v = out[(size_t)t * DM + i];
        if (s0 >= 0) v += w0 * g_Y[(size_t)s0 * DM + i];
        if (s1 >= 0) v += w1 * g_Y[(size_t)s1 * DM + i];
        out[(size_t)t * DM + i] = v;
    }
}

// ---------------- launch ----------------
extern "C" void kernel_launch(void* const* d_in, const int* in_sizes, int n_in,
                              void* d_out, int out_size) {
    const float* hs  = (const float*)d_in[0];
    const float* Wg  = (const float*)d_in[1];
    const float* w1  = (const float*)d_in[2];
    const float* w3  = (const float*)d_in[3];
    const float* w2  = (const float*)d_in[4];
    const float* ws1 = (const float*)d_in[5];
    const float* ws3 = (const float*)d_in[6];
    const float* ws2 = (const float*)d_in[7];
    float* out = (float*)d_out;

    cudaFuncSetAttribute(swiglu_tc<0>, cudaFuncAttributeMaxDynamicSharedMemorySize, SMEM_BYTES);
    cudaFuncSetAttribute(swiglu_tc<1>, cudaFuncAttributeMaxDynamicSharedMemorySize, SMEM_BYTES);
    cudaFuncSetAttribute(plain_tc<0>,  cudaFuncAttributeMaxDynamicSharedMemorySize, SMEM_BYTES);
    cudaFuncSetAttribute(plain_tc<1>,  cudaFuncAttributeMaxDynamicSharedMemorySize, SMEM_BYTES);

    zero_cnt_kernel<<<1, 32>>>();

    dim3 wb(32, 8);
    wsplit_kernel<0><<<dim3(DFF / 32, DM / 32, NE), wb>>>(w1, DM, DFF);
    wsplit_kernel<1><<<dim3(DFF / 32, DM / 32, NE), wb>>>(w3, DM, DFF);
    wsplit_kernel<2><<<dim3(DM / 32, DFF / 32, NE), wb>>>(w2, DFF, DM);
    wsplit_kernel<3><<<dim3(DFS / 32, DM / 32, 1), wb>>>(ws1, DM, DFS);
    wsplit_kernel<4><<<dim3(DFS / 32, DM / 32, 1), wb>>>(ws3, DM, DFS);
    wsplit_kernel<5><<<dim3(DM / 32, DFS / 32, 1), wb>>>(ws2, DFS, DM);

    router_kernel<<<T_TOK / 8, 256>>>(hs, Wg);

    // expert path
    swiglu_tc<0><<<dim3(DFF / 64, CAP / 128, NE), 256, SMEM_BYTES>>>(nullptr);
    plain_tc<0><<<dim3(DM / 128, CAP / 128, NE), 256, SMEM_BYTES>>>(nullptr);

    // shared expert path (down-proj writes full d_out, clearing the poison)
    swiglu_tc<1><<<dim3(DFS / 64, T_TOK / 128, 1), 256, SMEM_BYTES>>>(hs);
    plain_tc<1><<<dim3(DM / 128, T_TOK / 128, 1), 256, SMEM_BYTES>>>(out);

    combine_kernel<<<T_TOK, 256>>>(out);
}

// round 4
// speedup vs baseline: 2.6819x; 1.7084x over previous
#include <cuda_runtime.h>
#include <cuda_bf16.h>
#include <cstdint>
#include <math.h>

#define T_TOK 4096
#define DM    1024
#define NE    16
#define CAP   1024
#define DFF   512
#define DFS   1024

// ---------------- scratch (static device globals; no allocation) ----------------
__device__ int   g_cnt[NE];
__device__ int   g_slot[T_TOK * 2];
__device__ float g_wt[T_TOK * 2];
__device__ float g_Y [(size_t)NE * CAP * DM];   // expert outputs (fp32)

// activations as bf16 hi/lo (converted once, outside GEMM mainloops)
__device__ __nv_bfloat16 g_Xh [(size_t)NE * CAP * DM],  g_Xl [(size_t)NE * CAP * DM];
__device__ __nv_bfloat16 g_Hh [(size_t)NE * CAP * DFF], g_Hl [(size_t)NE * CAP * DFF];
__device__ __nv_bfloat16 g_hsh[(size_t)T_TOK * DM],     g_hsl[(size_t)T_TOK * DM];
__device__ __nv_bfloat16 g_Hsh[(size_t)T_TOK * DFS],    g_Hsl[(size_t)T_TOK * DFS];

// bf16 hi/lo split weights, transposed to [N, K] per expert
__device__ __nv_bfloat16 g_w1h[(size_t)NE * DFF * DM], g_w1l[(size_t)NE * DFF * DM];
__device__ __nv_bfloat16 g_w3h[(size_t)NE * DFF * DM], g_w3l[(size_t)NE * DFF * DM];
__device__ __nv_bfloat16 g_w2h[(size_t)NE * DM * DFF], g_w2l[(size_t)NE * DM * DFF];
__device__ __nv_bfloat16 g_ws1h[(size_t)DFS * DM], g_ws1l[(size_t)DFS * DM];
__device__ __nv_bfloat16 g_ws3h[(size_t)DFS * DM], g_ws3l[(size_t)DFS * DM];
__device__ __nv_bfloat16 g_ws2h[(size_t)DM * DFS], g_ws2l[(size_t)DM * DFS];

// ---------------- helpers ----------------
__device__ __forceinline__ uint32_t smem_u32(const void* p) {
    uint32_t r;
    asm("{ .reg .u64 t; cvta.to.shared.u64 t, %1; cvt.u32.u64 %0, t; }" : "=r"(r) : "l"(p));
    return r;
}

#define LDSM_X4(r0, r1, r2, r3, addr) \
    asm volatile("ldmatrix.sync.aligned.m8n8.x4.shared.b16 {%0,%1,%2,%3}, [%4];" \
                 : "=r"(r0), "=r"(r1), "=r"(r2), "=r"(r3) : "r"(addr))

__device__ __forceinline__ void mma_bf16(float* c, const uint32_t* a, const uint32_t* b) {
    asm volatile("mma.sync.aligned.m16n8k16.row.col.f32.bf16.bf16.f32 "
                 "{%0,%1,%2,%3}, {%4,%5,%6,%7}, {%8,%9}, {%0,%1,%2,%3};"
                 : "+f"(c[0]), "+f"(c[1]), "+f"(c[2]), "+f"(c[3])
                 : "r"(a[0]), "r"(a[1]), "r"(a[2]), "r"(a[3]), "r"(b[0]), "r"(b[1]));
}

#define CP_ASYNC16(dst, src) \
    asm volatile("{ .reg .u64 g; cvta.to.global.u64 g, %1; " \
                 "cp.async.cg.shared.global [%0], [g], 16; }" \
                 :: "r"(dst), "l"(src) : "memory")
#define CP_COMMIT() asm volatile("cp.async.commit_group;" ::: "memory")
#define CP_WAIT(n)  asm volatile("cp.async.wait_group %0;" :: "n"(n) : "memory")

// swizzled smem address: 128B rows of 8x16B chunks, chunk ^= (row & 7)
__device__ __forceinline__ uint32_t swz(uint32_t base, int r, int byteoff) {
    return base + (uint32_t)(r * 128) + (uint32_t)(((((byteoff >> 4) ^ (r & 7)) << 4)) | (byteoff & 15));
}

// fp32 -> (bf16 hi, bf16 lo) packed pairs
__device__ __forceinline__ void split2(float a, float b, uint32_t& h, uint32_t& l) {
    __nv_bfloat162 H = __floats2bfloat162_rn(a, b);
    float2 Hf = __bfloat1622float2(H);
    __nv_bfloat162 L = __floats2bfloat162_rn(a - Hf.x, b - Hf.y);
    __builtin_memcpy(&h, &H, 4);
    __builtin_memcpy(&l, &L, 4);
}

// cp.async one 128x64-bf16 tile from row-major [*, ldk] into swizzled smem (256 thr)
__device__ __forceinline__ void cpa_tile(const __nv_bfloat16* __restrict__ src, int ldk, uint32_t dst) {
    const int tid = threadIdx.x;
#pragma unroll
    for (int k = 0; k < 4; k++) {
        const int i = tid + k * 256;
        const int r = i >> 3, c = i & 7;
        const uint32_t off = (uint32_t)(r * 128 + ((c ^ (r & 7)) << 4));
        CP_ASYNC16(dst + off, src + (size_t)r * ldk + c * 8);
    }
}

// dual-source variant: rows 0..63 from b1, 64..127 from b3 (SwiGLU B tile)
__device__ __forceinline__ void cpa_tile_dual(const __nv_bfloat16* __restrict__ b1,
                                              const __nv_bfloat16* __restrict__ b3,
                                              int ldk, uint32_t dst) {
    const int tid = threadIdx.x;
#pragma unroll
    for (int k = 0; k < 4; k++) {
        const int i = tid + k * 256;
        const int r = i >> 3, c = i & 7;
        const __nv_bfloat16* s = (r < 64) ? b1 + (size_t)r * ldk + c * 8
                                          : b3 + (size_t)(r - 64) * ldk + c * 8;
        const uint32_t off = (uint32_t)(r * 128 + ((c ^ (r & 7)) << 4));
        CP_ASYNC16(dst + off, s);
    }
}

#define NSTAGE 3
#define STAGE_BYTES 65536           // Ah(16K)+Al(16K)+Bh(16K)+Bl(16K)
#define SMEM_BYTES (NSTAGE * STAGE_BYTES + 1024)

// ---------------- weight transpose + bf16 split prepass ----------------
template <int ID>
__global__ void wsplit_kernel(const float* __restrict__ W, int K, int N) {
    __nv_bfloat16 *oh, *ol;
    if (ID == 0) { oh = g_w1h;  ol = g_w1l;  }
    if (ID == 1) { oh = g_w3h;  ol = g_w3l;  }
    if (ID == 2) { oh = g_w2h;  ol = g_w2l;  }
    if (ID == 3) { oh = g_ws1h; ol = g_ws1l; }
    if (ID == 4) { oh = g_ws3h; ol = g_ws3l; }
    if (ID == 5) { oh = g_ws2h; ol = g_ws2l; }
    const size_t eoff = (size_t)blockIdx.z * K * N;
    W += eoff; oh += eoff; ol += eoff;

    __shared__ float t[32][33];
    const int kb = blockIdx.y * 32, nb = blockIdx.x * 32;
    const int tx = threadIdx.x, ty = threadIdx.y;
#pragma unroll
    for (int i = 0; i < 4; i++)
        t[ty + 8 * i][tx] = W[(size_t)(kb + ty + 8 * i) * N + nb + tx];
    __syncthreads();
#pragma unroll
    for (int i = 0; i < 4; i++) {
        const int n = nb + ty + 8 * i;
        float v = t[tx][ty + 8 * i];
        __nv_bfloat16 hi = __float2bfloat16(v);
        __nv_bfloat16 lo = __float2bfloat16(v - __bfloat162float(hi));
        oh[(size_t)n * K + kb + tx] = hi;
        ol[(size_t)n * K + kb + tx] = lo;
    }
}

// ---------------- counters reset ----------------
__global__ void zero_cnt_kernel() {
    if (threadIdx.x < NE) g_cnt[threadIdx.x] = 0;
}

// ---------------- router: logits/top2/slots + bf16-split gather ----------------
__global__ void router_kernel(const float* __restrict__ hs, const float* __restrict__ Wg) {
    __shared__ float sW[NE * 513];
    const int tid = threadIdx.x, lane = tid & 31, wid = tid >> 5;
    const int t = blockIdx.x * 8 + wid;

    float hreg[32];
#pragma unroll
    for (int j = 0; j < 32; j++) hreg[j] = hs[(size_t)t * DM + j * 32 + lane];

    // split once into bf16 hi/lo registers
    __nv_bfloat16 hh[32], hl[32];
#pragma unroll
    for (int j = 0; j < 32; j++) {
        hh[j] = __float2bfloat16(hreg[j]);
        hl[j] = __float2bfloat16(hreg[j] - __bfloat162float(hh[j]));
    }
    // shared-path A (always)
#pragma unroll
    for (int j = 0; j < 32; j++) {
        g_hsh[(size_t)t * DM + j * 32 + lane] = hh[j];
        g_hsl[(size_t)t * DM + j * 32 + lane] = hl[j];
    }

    float plog[NE];
#pragma unroll
    for (int e = 0; e < NE; e++) plog[e] = 0.f;

    for (int c = 0; c < 2; c++) {
        __syncthreads();
        for (int i = tid; i < 512 * NE; i += 256) {
            int d = i >> 4, e = i & 15;
            sW[e * 513 + d] = Wg[(size_t)c * 8192 + i];
        }
        __syncthreads();
#pragma unroll
        for (int e = 0; e < NE; e++) {
            float s = 0.f;
#pragma unroll
            for (int j = 0; j < 16; j++)
                s += hreg[c * 16 + j] * sW[e * 513 + j * 32 + lane];
            plog[e] += s;
        }
    }
#pragma unroll
    for (int e = 0; e < NE; e++) {
        float v = plog[e];
#pragma unroll
        for (int o = 16; o > 0; o >>= 1) v += __shfl_xor_sync(0xffffffffu, v, o);
        plog[e] = v;
    }
    float mx = plog[0];
#pragma unroll
    for (int e = 1; e < NE; e++) mx = fmaxf(mx, plog[e]);
#pragma unroll
    for (int e = 0; e < NE; e++) plog[e] = expf(plog[e] - mx);
    int e0 = 0; float p0 = plog[0];
#pragma unroll
    for (int e = 1; e < NE; e++) if (plog[e] > p0) { p0 = plog[e]; e0 = e; }
    int e1 = 0; float p1 = -1.f;
#pragma unroll
    for (int e = 0; e < NE; e++) if (e != e0 && plog[e] > p1) { p1 = plog[e]; e1 = e; }
    const float rnorm = 1.f / (p0 + p1);
    const float w0 = p0 * rnorm, w1 = p1 * rnorm;

    int s0 = 0, s1 = 0;
    if (lane == 0) {
        int pos = atomicAdd(&g_cnt[e0], 1);
        s0 = (pos < CAP) ? e0 * CAP + pos : -1;
        pos = atomicAdd(&g_cnt[e1], 1);
        s1 = (pos < CAP) ? e1 * CAP + pos : -1;
        g_slot[t * 2] = s0; g_slot[t * 2 + 1] = s1;
        g_wt[t * 2] = w0;   g_wt[t * 2 + 1] = w1;
    }
    s0 = __shfl_sync(0xffffffffu, s0, 0);
    s1 = __shfl_sync(0xffffffffu, s1, 0);
    if (s0 >= 0) {
#pragma unroll
        for (int j = 0; j < 32; j++) {
            g_Xh[(size_t)s0 * DM + j * 32 + lane] = hh[j];
            g_Xl[(size_t)s0 * DM + j * 32 + lane] = hl[j];
        }
    }
    if (s1 >= 0) {
#pragma unroll
        for (int j = 0; j < 32; j++) {
            g_Xh[(size_t)s1 * DM + j * 32 + lane] = hh[j];
            g_Xl[(size_t)s1 * DM + j * 32 + lane] = hl[j];
        }
    }
}

// ======================= HMMA GEMM kernels (3-term bf16 split, cp.async 3-stage) =======================

__device__ __forceinline__ void ld_a_frags(uint32_t sA, int m0, int lane, int kk, uint32_t a[2][4]) {
    const int r = m0 + (lane & 15);
    const int byte = kk * 32 + ((lane >> 4) << 4);
    LDSM_X4(a[0][0], a[0][1], a[0][2], a[0][3], swz(sA, r, byte));
    LDSM_X4(a[1][0], a[1][1], a[1][2], a[1][3], swz(sA, r + 16, byte));
}

__device__ __forceinline__ void ld_b_pair(uint32_t sB, int nb, int lane, int kk, uint32_t b[4]) {
    const int r = nb + ((lane >> 4) << 3) + (lane & 7);
    const int byte = kk * 32 + (((lane >> 3) & 1) << 4);
    LDSM_X4(b[0], b[1], b[2], b[3], swz(sB, r, byte));
}

__device__ __forceinline__ float silu_f(float x) {
    return x / (1.f + __expf(-x));
}

// compute one K-64 stage into acc (shared by both kernels; swiglu uses SWIGLU_N mapping)
template <int SWIGLU>
__device__ __forceinline__ void compute_stage(uint32_t st, int m0, int warpN, int lane,
                                              float acc[2][8][4]) {
    const uint32_t sAh = st, sAl = st + 16384, sBh = st + 32768, sBl = st + 49152;
#pragma unroll
    for (int kk = 0; kk < 4; kk++) {
        uint32_t ah[2][4], al[2][4], bh[4][4], bl[4][4];
        ld_a_frags(sAh, m0, lane, kk, ah);
        ld_a_frags(sAl, m0, lane, kk, al);
#pragma unroll
        for (int p = 0; p < 4; p++) {
            const int nb = SWIGLU ? ((p < 2) ? (warpN * 32 + p * 16) : (64 + warpN * 32 + (p - 2) * 16))
                                  : (warpN * 64 + p * 16);
            ld_b_pair(sBh, nb, lane, kk, bh[p]);
            ld_b_pair(sBl, nb, lane, kk, bl[p]);
        }
#pragma unroll
        for (int mt = 0; mt < 2; mt++)
#pragma unroll
            for (int nt = 0; nt < 8; nt++) {
                const uint32_t* ph = &bh[nt >> 1][(nt & 1) * 2];
                const uint32_t* pl = &bl[nt >> 1][(nt & 1) * 2];
                mma_bf16(acc[mt][nt], ah[mt], ph);
                mma_bf16(acc[mt][nt], ah[mt], pl);
                mma_bf16(acc[mt][nt], al[mt], ph);
            }
    }
}

// ---------------- SwiGLU: H(bf16 hi/lo) = silu(A@W1) * (A@W3) ----------------
template <int MODE>
__global__ __launch_bounds__(256, 1) void swiglu_tc() {
    constexpr int KT = DM;
    constexpr int NS = KT / 64;
    constexpr int NTOT = (MODE == 0) ? DFF : DFS;

    const int e = blockIdx.z;
    const __nv_bfloat16 *Ah, *Al, *B1h, *B1l, *B3h, *B3l;
    __nv_bfloat16 *Hh, *Hl;
    int valid;
    if (MODE == 0) {
        valid = min(g_cnt[e], CAP);
        Ah = g_Xh + (size_t)e * CAP * DM;  Al = g_Xl + (size_t)e * CAP * DM;
        B1h = g_w1h + (size_t)e * DFF * DM;  B1l = g_w1l + (size_t)e * DFF * DM;
        B3h = g_w3h + (size_t)e * DFF * DM;  B3l = g_w3l + (size_t)e * DFF * DM;
        Hh = g_Hh + (size_t)e * CAP * DFF;   Hl = g_Hl + (size_t)e * CAP * DFF;
    } else {
        valid = T_TOK;
        Ah = g_hsh; Al = g_hsl;
        B1h = g_ws1h; B1l = g_ws1l; B3h = g_ws3h; B3l = g_ws3l;
        Hh = g_Hsh; Hl = g_Hsl;
    }
    const int row0 = blockIdx.y * 128;
    if (row0 >= valid) return;
    const int col0 = blockIdx.x * 64;

    extern __shared__ char smem[];
    const uint32_t sb = (smem_u32(smem) + 1023u) & ~1023u;

    const int tid = threadIdx.x, lane = tid & 31, warp = tid >> 5;
    const int warpM = warp & 3, warpN = warp >> 2;
    const int m0 = warpM * 32;

    float acc[2][8][4];
#pragma unroll
    for (int i = 0; i < 2; i++)
#pragma unroll
        for (int j = 0; j < 8; j++)
#pragma unroll
            for (int q = 0; q < 4; q++) acc[i][j][q] = 0.f;

    // prologue: stages 0..NSTAGE-2
#pragma unroll
    for (int s = 0; s < NSTAGE - 1; s++) {
        const uint32_t st = sb + s * STAGE_BYTES;
        const int k0 = s * 64;
        cpa_tile(Ah + (size_t)row0 * KT + k0, KT, st);
        cpa_tile(Al + (size_t)row0 * KT + k0, KT, st + 16384);
        cpa_tile_dual(B1h + (size_t)col0 * KT + k0, B3h + (size_t)col0 * KT + k0, KT, st + 32768);
        cpa_tile_dual(B1l + (size_t)col0 * KT + k0, B3l + (size_t)col0 * KT + k0, KT, st + 49152);
        CP_COMMIT();
    }

    for (int s = 0; s < NS; s++) {
        if (s + NSTAGE - 1 < NS) {
            const int sp = s + NSTAGE - 1;
            const uint32_t st = sb + (sp % NSTAGE) * STAGE_BYTES;
            const int k0 = sp * 64;
            cpa_tile(Ah + (size_t)row0 * KT + k0, KT, st);
            cpa_tile(Al + (size_t)row0 * KT + k0, KT, st + 16384);
            cpa_tile_dual(B1h + (size_t)col0 * KT + k0, B3h + (size_t)col0 * KT + k0, KT, st + 32768);
            cpa_tile_dual(B1l + (size_t)col0 * KT + k0, B3l + (size_t)col0 * KT + k0, KT, st + 49152);
            CP_COMMIT();
            CP_WAIT(NSTAGE - 2);
        } else {
            CP_WAIT(0);
        }
        __syncthreads();
        compute_stage<1>(sb + (s % NSTAGE) * STAGE_BYTES, m0, warpN, lane, acc);
        __syncthreads();
    }

    // epilogue: nt 0..3 -> W1, nt 4..7 -> W3; write bf16 hi/lo pairs
#pragma unroll
    for (int mt = 0; mt < 2; mt++) {
        const int rbase = row0 + m0 + mt * 16 + (lane >> 2);
#pragma unroll
        for (int nt = 0; nt < 4; nt++) {
            const int col = col0 + warpN * 32 + nt * 8 + (lane & 3) * 2;
            float* c1 = acc[mt][nt];
            float* c3 = acc[mt][nt + 4];
            float o00 = silu_f(c1[0]) * c3[0], o01 = silu_f(c1[1]) * c3[1];
            float o10 = silu_f(c1[2]) * c3[2], o11 = silu_f(c1[3]) * c3[3];
            uint32_t h0, l0, h1, l1;
            split2(o00, o01, h0, l0);
            split2(o10, o11, h1, l1);
            *reinterpret_cast<uint32_t*>(Hh + (size_t)rbase * NTOT + col) = h0;
            *reinterpret_cast<uint32_t*>(Hl + (size_t)rbase * NTOT + col) = l0;
            *reinterpret_cast<uint32_t*>(Hh + (size_t)(rbase + 8) * NTOT + col) = h1;
            *reinterpret_cast<uint32_t*>(Hl + (size_t)(rbase + 8) * NTOT + col) = l1;
        }
    }
}

// ---------------- plain GEMM: O(fp32) = A @ W ----------------
template <int MODE>
__global__ __launch_bounds__(256, 1) void plain_tc(float* __restrict__ Oext) {
    constexpr int KT = (MODE == 0) ? DFF : DFS;
    constexpr int NS = KT / 64;

    const int e = blockIdx.z;
    const __nv_bfloat16 *Ah, *Al, *Bh, *Bl;
    float* O;
    int valid;
    if (MODE == 0) {
        valid = min(g_cnt[e], CAP);
        Ah = g_Hh + (size_t)e * CAP * DFF;  Al = g_Hl + (size_t)e * CAP * DFF;
        Bh = g_w2h + (size_t)e * DM * DFF;  Bl = g_w2l + (size_t)e * DM * DFF;
        O  = g_Y + (size_t)e * CAP * DM;
    } else {
        valid = T_TOK;
        Ah = g_Hsh; Al = g_Hsl;
        Bh = g_ws2h; Bl = g_ws2l;
        O = Oext;
    }
    const int row0 = blockIdx.y * 128;
    if (row0 >= valid) return;
    const int col0 = blockIdx.x * 128;

    extern __shared__ char smem[];
    const uint32_t sb = (smem_u32(smem) + 1023u) & ~1023u;

    const int tid = threadIdx.x, lane = tid & 31, warp = tid >> 5;
    const int warpM = warp & 3, warpN = warp >> 2;
    const int m0 = warpM * 32;

    float acc[2][8][4];
#pragma unroll
    for (int i = 0; i < 2; i++)
#pragma unroll
        for (int j = 0; j < 8; j++)
#pragma unroll
            for (int q = 0; q < 4; q++) acc[i][j][q] = 0.f;

#pragma unroll
    for (int s = 0; s < NSTAGE - 1; s++) {
        const uint32_t st = sb + s * STAGE_BYTES;
        const int k0 = s * 64;
        cpa_tile(Ah + (size_t)row0 * KT + k0, KT, st);
        cpa_tile(Al + (size_t)row0 * KT + k0, KT, st + 16384);
        cpa_tile(Bh + (size_t)col0 * KT + k0, KT, st + 32768);
        cpa_tile(Bl + (size_t)col0 * KT + k0, KT, st + 49152);
        CP_COMMIT();
    }

    for (int s = 0; s < NS; s++) {
        if (s + NSTAGE - 1 < NS) {
            const int sp = s + NSTAGE - 1;
            const uint32_t st = sb + (sp % NSTAGE) * STAGE_BYTES;
            const int k0 = sp * 64;
            cpa_tile(Ah + (size_t)row0 * KT + k0, KT, st);
            cpa_tile(Al + (size_t)row0 * KT + k0, KT, st + 16384);
            cpa_tile(Bh + (size_t)col0 * KT + k0, KT, st + 32768);
            cpa_tile(Bl + (size_t)col0 * KT + k0, KT, st + 49152);
            CP_COMMIT();
            CP_WAIT(NSTAGE - 2);
        } else {
            CP_WAIT(0);
        }
        __syncthreads();
        compute_stage<0>(sb + (s % NSTAGE) * STAGE_BYTES, m0, warpN, lane, acc);
        __syncthreads();
    }

#pragma unroll
    for (int mt = 0; mt < 2; mt++) {
        const int rbase = row0 + m0 + mt * 16 + (lane >> 2);
#pragma unroll
        for (int nt = 0; nt < 8; nt++) {
            const int col = col0 + warpN * 64 + nt * 8 + (lane & 3) * 2;
            float* c = acc[mt][nt];
            *reinterpret_cast<float2*>(O + (size_t)rbase * DM + col) = make_float2(c[0], c[1]);
            *reinterpret_cast<float2*>(O + (size_t)(rbase + 8) * DM + col) = make_float2(c[2], c[3]);
        }
    }
}

// ---------------- combine ----------------
__global__ void combine_kernel(float* __restrict__ out) {
    const int t = blockIdx.x;
    const int s0 = g_slot[2 * t], s1 = g_slot[2 * t + 1];
    const float w0 = g_wt[2 * t], w1 = g_wt[2 * t + 1];
    for (int i = threadIdx.x; i < DM; i += 256) {
        float v = out[(size_t)t * DM + i];
        if (s0 >= 0) v += w0 * g_Y[(size_t)s0 * DM + i];
        if (s1 >= 0) v += w1 * g_Y[(size_t)s1 * DM + i];
        out[(size_t)t * DM + i] = v;
    }
}

// ---------------- launch ----------------
extern "C" void kernel_launch(void* const* d_in, const int* in_sizes, int n_in,
                              void* d_out, int out_size) {
    const float* hs  = (const float*)d_in[0];
    const float* Wg  = (const float*)d_in[1];
    const float* w1  = (const float*)d_in[2];
    const float* w3  = (const float*)d_in[3];
    const float* w2  = (const float*)d_in[4];
    const float* ws1 = (const float*)d_in[5];
    const float* ws3 = (const float*)d_in[6];
    const float* ws2 = (const float*)d_in[7];
    float* out = (float*)d_out;

    cudaFuncSetAttribute(swiglu_tc<0>, cudaFuncAttributeMaxDynamicSharedMemorySize, SMEM_BYTES);
    cudaFuncSetAttribute(swiglu_tc<1>, cudaFuncAttributeMaxDynamicSharedMemorySize, SMEM_BYTES);
    cudaFuncSetAttribute(plain_tc<0>,  cudaFuncAttributeMaxDynamicSharedMemorySize, SMEM_BYTES);
    cudaFuncSetAttribute(plain_tc<1>,  cudaFuncAttributeMaxDynamicSharedMemorySize, SMEM_BYTES);

    zero_cnt_kernel<<<1, 32>>>();

    dim3 wb(32, 8);
    wsplit_kernel<0><<<dim3(DFF / 32, DM / 32, NE), wb>>>(w1, DM, DFF);
    wsplit_kernel<1><<<dim3(DFF / 32, DM / 32, NE), wb>>>(w3, DM, DFF);
    wsplit_kernel<2><<<dim3(DM / 32, DFF / 32, NE), wb>>>(w2, DFF, DM);
    wsplit_kernel<3><<<dim3(DFS / 32, DM / 32, 1), wb>>>(ws1, DM, DFS);
    wsplit_kernel<4><<<dim3(DFS / 32, DM / 32, 1), wb>>>(ws3, DM, DFS);
    wsplit_kernel<5><<<dim3(DM / 32, DFS / 32, 1), wb>>>(ws2, DFS, DM);

    router_kernel<<<T_TOK / 8, 256>>>(hs, Wg);

    // expert path
    swiglu_tc<0><<<dim3(DFF / 64, CAP / 128, NE), 256, SMEM_BYTES>>>();
    plain_tc<0><<<dim3(DM / 128, CAP / 128, NE), 256, SMEM_BYTES>>>(nullptr);

    // shared expert path (down-proj writes full d_out, clearing the poison)
    swiglu_tc<1><<<dim3(DFS / 64, T_TOK / 128, 1), 256, SMEM_BYTES>>>();
    plain_tc<1><<<dim3(DM / 128, T_TOK / 128, 1), 256, SMEM_BYTES>>>(out);

    combine_kernel<<<T_TOK, 256>>>(out);
}

// round 5
// speedup vs baseline: 2.7335x; 1.0192x over previous
#include <cuda_runtime.h>
#include <cuda_bf16.h>
#include <cstdint>
#include <math.h>

#define T_TOK 4096
#define DM    1024
#define NE    16
#define CAP   1024
#define DFF   512
#define DFS   1024

// ---------------- scratch (static device globals; no allocation) ----------------
__device__ int   g_cnt[NE];
__device__ int   g_slot[T_TOK * 2];
__device__ float g_wt[T_TOK * 2];
__device__ float g_Y [(size_t)NE * CAP * DM];   // expert outputs (fp32)

// activations as bf16 hi/lo (converted once, outside GEMM mainloops)
__device__ __nv_bfloat16 g_Xh [(size_t)NE * CAP * DM],  g_Xl [(size_t)NE * CAP * DM];
__device__ __nv_bfloat16 g_Hh [(size_t)NE * CAP * DFF], g_Hl [(size_t)NE * CAP * DFF];
__device__ __nv_bfloat16 g_hsh[(size_t)T_TOK * DM],     g_hsl[(size_t)T_TOK * DM];
__device__ __nv_bfloat16 g_Hsh[(size_t)T_TOK * DFS],    g_Hsl[(size_t)T_TOK * DFS];

// bf16 hi/lo split weights, transposed to [N, K] per expert
__device__ __nv_bfloat16 g_w1h[(size_t)NE * DFF * DM], g_w1l[(size_t)NE * DFF * DM];
__device__ __nv_bfloat16 g_w3h[(size_t)NE * DFF * DM], g_w3l[(size_t)NE * DFF * DM];
__device__ __nv_bfloat16 g_w2h[(size_t)NE * DM * DFF], g_w2l[(size_t)NE * DM * DFF];
__device__ __nv_bfloat16 g_ws1h[(size_t)DFS * DM], g_ws1l[(size_t)DFS * DM];
__device__ __nv_bfloat16 g_ws3h[(size_t)DFS * DM], g_ws3l[(size_t)DFS * DM];
__device__ __nv_bfloat16 g_ws2h[(size_t)DM * DFS], g_ws2l[(size_t)DM * DFS];

// ---------------- helpers ----------------
__device__ __forceinline__ uint32_t smem_u32(const void* p) {
    uint32_t r;
    asm("{ .reg .u64 t; cvta.to.shared.u64 t, %1; cvt.u32.u64 %0, t; }" : "=r"(r) : "l"(p));
    return r;
}

#define LDSM_X4(r0, r1, r2, r3, addr) \
    asm volatile("ldmatrix.sync.aligned.m8n8.x4.shared.b16 {%0,%1,%2,%3}, [%4];" \
                 : "=r"(r0), "=r"(r1), "=r"(r2), "=r"(r3) : "r"(addr))

__device__ __forceinline__ void mma_bf16(float* c, const uint32_t* a, const uint32_t* b) {
    asm volatile("mma.sync.aligned.m16n8k16.row.col.f32.bf16.bf16.f32 "
                 "{%0,%1,%2,%3}, {%4,%5,%6,%7}, {%8,%9}, {%0,%1,%2,%3};"
                 : "+f"(c[0]), "+f"(c[1]), "+f"(c[2]), "+f"(c[3])
                 : "r"(a[0]), "r"(a[1]), "r"(a[2]), "r"(a[3]), "r"(b[0]), "r"(b[1]));
}

#define CP_ASYNC16(dst, src) \
    asm volatile("{ .reg .u64 g; cvta.to.global.u64 g, %1; " \
                 "cp.async.cg.shared.global [%0], [g], 16; }" \
                 :: "r"(dst), "l"(src) : "memory")
#define CP_COMMIT() asm volatile("cp.async.commit_group;" ::: "memory")
#define CP_WAIT(n)  asm volatile("cp.async.wait_group %0;" :: "n"(n) : "memory")

// swizzled smem address: 128B rows of 8x16B chunks, chunk ^= (row & 7)
__device__ __forceinline__ uint32_t swz(uint32_t base, int r, int byteoff) {
    return base + (uint32_t)(r * 128) + (uint32_t)(((((byteoff >> 4) ^ (r & 7)) << 4)) | (byteoff & 15));
}

// fp32 -> (bf16 hi, bf16 lo) packed pairs
__device__ __forceinline__ void split2(float a, float b, uint32_t& h, uint32_t& l) {
    __nv_bfloat162 H = __floats2bfloat162_rn(a, b);
    float2 Hf = __bfloat1622float2(H);
    __nv_bfloat162 L = __floats2bfloat162_rn(a - Hf.x, b - Hf.y);
    __builtin_memcpy(&h, &H, 4);
    __builtin_memcpy(&l, &L, 4);
}

// cp.async one 128x64-bf16 tile from row-major [*, ldk] into swizzled smem (256 thr)
__device__ __forceinline__ void cpa_tile(const __nv_bfloat16* __restrict__ src, int ldk, uint32_t dst) {
    const int tid = threadIdx.x;
#pragma unroll
    for (int k = 0; k < 4; k++) {
        const int i = tid + k * 256;
        const int r = i >> 3, c = i & 7;
        const uint32_t off = (uint32_t)(r * 128 + ((c ^ (r & 7)) << 4));
        CP_ASYNC16(dst + off, src + (size_t)r * ldk + c * 8);
    }
}

// dual-source variant: rows 0..63 from b1, 64..127 from b3 (SwiGLU B tile)
__device__ __forceinline__ void cpa_tile_dual(const __nv_bfloat16* __restrict__ b1,
                                              const __nv_bfloat16* __restrict__ b3,
                                              int ldk, uint32_t dst) {
    const int tid = threadIdx.x;
#pragma unroll
    for (int k = 0; k < 4; k++) {
        const int i = tid + k * 256;
        const int r = i >> 3, c = i & 7;
        const __nv_bfloat16* s = (r < 64) ? b1 + (size_t)r * ldk + c * 8
                                          : b3 + (size_t)(r - 64) * ldk + c * 8;
        const uint32_t off = (uint32_t)(r * 128 + ((c ^ (r & 7)) << 4));
        CP_ASYNC16(dst + off, s);
    }
}

#define NSTAGE 3
#define STAGE_BYTES 65536           // Ah(16K)+Al(16K)+Bh(16K)+Bl(16K)
#define SMEM_BYTES (NSTAGE * STAGE_BYTES + 1024)

// ---------------- merged weight transpose + bf16 split prepass (one launch) ----------------
// tile counts (32x32 tiles): w1 8192 | w3 8192 | w2 8192 | ws1 1024 | ws3 1024 | ws2 1024
__global__ void wsplit_all(const float* __restrict__ w1, const float* __restrict__ w3,
                           const float* __restrict__ w2, const float* __restrict__ ws1,
                           const float* __restrict__ ws3, const float* __restrict__ ws2) {
    int id = blockIdx.x;
    const float* W;
    __nv_bfloat16 *oh, *ol;
    int K, N, e, rem;
    if (id < 8192)        { W = w1;  oh = g_w1h;  ol = g_w1l;  K = DM;  N = DFF; e = id >> 9;  rem = id & 511; }
    else if (id < 16384)  { id -= 8192;  W = w3;  oh = g_w3h;  ol = g_w3l;  K = DM;  N = DFF; e = id >> 9;  rem = id & 511; }
    else if (id < 24576)  { id -= 16384; W = w2;  oh = g_w2h;  ol = g_w2l;  K = DFF; N = DM;  e = id >> 9;  rem = id & 511; }
    else if (id < 25600)  { id -= 24576; W = ws1; oh = g_ws1h; ol = g_ws1l; K = DM;  N = DFS; e = 0;        rem = id; }
    else if (id < 26624)  { id -= 25600; W = ws3; oh = g_ws3h; ol = g_ws3l; K = DM;  N = DFS; e = 0;        rem = id; }
    else                  { id -= 26624; W = ws2; oh = g_ws2h; ol = g_ws2l; K = DFS; N = DM;  e = 0;        rem = id; }
    const int ntiles_n = N >> 5;
    const int kb = (rem / ntiles_n) * 32, nb = (rem % ntiles_n) * 32;
    const size_t eoff = (size_t)e * K * N;
    W += eoff; oh += eoff; ol += eoff;

    __shared__ float t[32][33];
    const int tx = threadIdx.x, ty = threadIdx.y;
#pragma unroll
    for (int i = 0; i < 4; i++)
        t[ty + 8 * i][tx] = W[(size_t)(kb + ty + 8 * i) * N + nb + tx];
    __syncthreads();
#pragma unroll
    for (int i = 0; i < 4; i++) {
        const int n = nb + ty + 8 * i;
        float v = t[tx][ty + 8 * i];
        __nv_bfloat16 hi = __float2bfloat16(v);
        __nv_bfloat16 lo = __float2bfloat16(v - __bfloat162float(hi));
        oh[(size_t)n * K + kb + tx] = hi;
        ol[(size_t)n * K + kb + tx] = lo;
    }
}

// ---------------- counters reset ----------------
__global__ void zero_cnt_kernel() {
    if (threadIdx.x < NE) g_cnt[threadIdx.x] = 0;
}

// ---------------- router: logits/top2/slots + bf16-split gather ----------------
__global__ void router_kernel(const float* __restrict__ hs, const float* __restrict__ Wg) {
    __shared__ float sW[NE * 513];
    const int tid = threadIdx.x, lane = tid & 31, wid = tid >> 5;
    const int t = blockIdx.x * 8 + wid;

    float hreg[32];
#pragma unroll
    for (int j = 0; j < 32; j++) hreg[j] = hs[(size_t)t * DM + j * 32 + lane];

    __nv_bfloat16 hh[32], hl[32];
#pragma unroll
    for (int j = 0; j < 32; j++) {
        hh[j] = __float2bfloat16(hreg[j]);
        hl[j] = __float2bfloat16(hreg[j] - __bfloat162float(hh[j]));
    }
#pragma unroll
    for (int j = 0; j < 32; j++) {
        g_hsh[(size_t)t * DM + j * 32 + lane] = hh[j];
        g_hsl[(size_t)t * DM + j * 32 + lane] = hl[j];
    }

    float plog[NE];
#pragma unroll
    for (int e = 0; e < NE; e++) plog[e] = 0.f;

    for (int c = 0; c < 2; c++) {
        __syncthreads();
        for (int i = tid; i < 512 * NE; i += 256) {
            int d = i >> 4, e = i & 15;
            sW[e * 513 + d] = Wg[(size_t)c * 8192 + i];
        }
        __syncthreads();
#pragma unroll
        for (int e = 0; e < NE; e++) {
            float s = 0.f;
#pragma unroll
            for (int j = 0; j < 16; j++)
                s += hreg[c * 16 + j] * sW[e * 513 + j * 32 + lane];
            plog[e] += s;
        }
    }
#pragma unroll
    for (int e = 0; e < NE; e++) {
        float v = plog[e];
#pragma unroll
        for (int o = 16; o > 0; o >>= 1) v += __shfl_xor_sync(0xffffffffu, v, o);
        plog[e] = v;
    }
    float mx = plog[0];
#pragma unroll
    for (int e = 1; e < NE; e++) mx = fmaxf(mx, plog[e]);
#pragma unroll
    for (int e = 0; e < NE; e++) plog[e] = expf(plog[e] - mx);
    int e0 = 0; float p0 = plog[0];
#pragma unroll
    for (int e = 1; e < NE; e++) if (plog[e] > p0) { p0 = plog[e]; e0 = e; }
    int e1 = 0; float p1 = -1.f;
#pragma unroll
    for (int e = 0; e < NE; e++) if (e != e0 && plog[e] > p1) { p1 = plog[e]; e1 = e; }
    const float rnorm = 1.f / (p0 + p1);
    const float w0 = p0 * rnorm, w1 = p1 * rnorm;

    int s0 = 0, s1 = 0;
    if (lane == 0) {
        int pos = atomicAdd(&g_cnt[e0], 1);
        s0 = (pos < CAP) ? e0 * CAP + pos : -1;
        pos = atomicAdd(&g_cnt[e1], 1);
        s1 = (pos < CAP) ? e1 * CAP + pos : -1;
        g_slot[t * 2] = s0; g_slot[t * 2 + 1] = s1;
        g_wt[t * 2] = w0;   g_wt[t * 2 + 1] = w1;
    }
    s0 = __shfl_sync(0xffffffffu, s0, 0);
    s1 = __shfl_sync(0xffffffffu, s1, 0);
    if (s0 >= 0) {
#pragma unroll
        for (int j = 0; j < 32; j++) {
            g_Xh[(size_t)s0 * DM + j * 32 + lane] = hh[j];
            g_Xl[(size_t)s0 * DM + j * 32 + lane] = hl[j];
        }
    }
    if (s1 >= 0) {
#pragma unroll
        for (int j = 0; j < 32; j++) {
            g_Xh[(size_t)s1 * DM + j * 32 + lane] = hh[j];
            g_Xl[(size_t)s1 * DM + j * 32 + lane] = hl[j];
        }
    }
}

// ======================= HMMA GEMM kernels (3-term bf16 split, cp.async 3-stage, 1 sync/stage) =======================

__device__ __forceinline__ void ld_a_frags(uint32_t sA, int m0, int lane, int kk, uint32_t a[2][4]) {
    const int r = m0 + (lane & 15);
    const int byte = kk * 32 + ((lane >> 4) << 4);
    LDSM_X4(a[0][0], a[0][1], a[0][2], a[0][3], swz(sA, r, byte));
    LDSM_X4(a[1][0], a[1][1], a[1][2], a[1][3], swz(sA, r + 16, byte));
}

__device__ __forceinline__ void ld_b_pair(uint32_t sB, int nb, int lane, int kk, uint32_t b[4]) {
    const int r = nb + ((lane >> 4) << 3) + (lane & 7);
    const int byte = kk * 32 + (((lane >> 3) & 1) << 4);
    LDSM_X4(b[0], b[1], b[2], b[3], swz(sB, r, byte));
}

__device__ __forceinline__ float silu_f(float x) {
    return x / (1.f + __expf(-x));
}

template <int SWIGLU>
__device__ __forceinline__ void compute_stage(uint32_t st, int m0, int warpN, int lane,
                                              float acc[2][8][4]) {
    const uint32_t sAh = st, sAl = st + 16384, sBh = st + 32768, sBl = st + 49152;
#pragma unroll
    for (int kk = 0; kk < 4; kk++) {
        uint32_t ah[2][4], al[2][4], bh[4][4], bl[4][4];
        ld_a_frags(sAh, m0, lane, kk, ah);
        ld_a_frags(sAl, m0, lane, kk, al);
#pragma unroll
        for (int p = 0; p < 4; p++) {
            const int nb = SWIGLU ? ((p < 2) ? (warpN * 32 + p * 16) : (64 + warpN * 32 + (p - 2) * 16))
                                  : (warpN * 64 + p * 16);
            ld_b_pair(sBh, nb, lane, kk, bh[p]);
            ld_b_pair(sBl, nb, lane, kk, bl[p]);
        }
#pragma unroll
        for (int mt = 0; mt < 2; mt++)
#pragma unroll
            for (int nt = 0; nt < 8; nt++) {
                const uint32_t* ph = &bh[nt >> 1][(nt & 1) * 2];
                const uint32_t* pl = &bl[nt >> 1][(nt & 1) * 2];
                mma_bf16(acc[mt][nt], ah[mt], ph);
                mma_bf16(acc[mt][nt], ah[mt], pl);
                mma_bf16(acc[mt][nt], al[mt], ph);
            }
    }
}

// ---------------- SwiGLU: H(bf16 hi/lo) = silu(A@W1) * (A@W3) ----------------
template <int MODE>
__global__ __launch_bounds__(256, 1) void swiglu_tc() {
    constexpr int KT = DM;
    constexpr int NS = KT / 64;
    constexpr int NTOT = (MODE == 0) ? DFF : DFS;

    const int e = blockIdx.z;
    const __nv_bfloat16 *Ah, *Al, *B1h, *B1l, *B3h, *B3l;
    __nv_bfloat16 *Hh, *Hl;
    int valid;
    if (MODE == 0) {
        valid = min(g_cnt[e], CAP);
        Ah = g_Xh + (size_t)e * CAP * DM;  Al = g_Xl + (size_t)e * CAP * DM;
        B1h = g_w1h + (size_t)e * DFF * DM;  B1l = g_w1l + (size_t)e * DFF * DM;
        B3h = g_w3h + (size_t)e * DFF * DM;  B3l = g_w3l + (size_t)e * DFF * DM;
        Hh = g_Hh + (size_t)e * CAP * DFF;   Hl = g_Hl + (size_t)e * CAP * DFF;
    } else {
        valid = T_TOK;
        Ah = g_hsh; Al = g_hsl;
        B1h = g_ws1h; B1l = g_ws1l; B3h = g_ws3h; B3l = g_ws3l;
        Hh = g_Hsh; Hl = g_Hsl;
    }
    const int row0 = blockIdx.y * 128;
    if (row0 >= valid) return;
    const int col0 = blockIdx.x * 64;

    extern __shared__ char smem[];
    const uint32_t sb = (smem_u32(smem) + 1023u) & ~1023u;

    const int tid = threadIdx.x, lane = tid & 31, warp = tid >> 5;
    const int warpM = warp & 3, warpN = warp >> 2;
    const int m0 = warpM * 32;

    float acc[2][8][4];
#pragma unroll
    for (int i = 0; i < 2; i++)
#pragma unroll
        for (int j = 0; j < 8; j++)
#pragma unroll
            for (int q = 0; q < 4; q++) acc[i][j][q] = 0.f;

#pragma unroll
    for (int s = 0; s < NSTAGE - 1; s++) {
        const uint32_t st = sb + s * STAGE_BYTES;
        const int k0 = s * 64;
        cpa_tile(Ah + (size_t)row0 * KT + k0, KT, st);
        cpa_tile(Al + (size_t)row0 * KT + k0, KT, st + 16384);
        cpa_tile_dual(B1h + (size_t)col0 * KT + k0, B3h + (size_t)col0 * KT + k0, KT, st + 32768);
        cpa_tile_dual(B1l + (size_t)col0 * KT + k0, B3l + (size_t)col0 * KT + k0, KT, st + 49152);
        CP_COMMIT();
    }

    for (int s = 0; s < NS; s++) {
        if (s == NS - 1) { CP_WAIT(0); } else { CP_WAIT(1); }
        __syncthreads();
        if (s + NSTAGE - 1 < NS) {
            const int sp = s + NSTAGE - 1;
            const uint32_t st = sb + (sp % NSTAGE) * STAGE_BYTES;
            const int k0 = sp * 64;
            cpa_tile(Ah + (size_t)row0 * KT + k0, KT, st);
            cpa_tile(Al + (size_t)row0 * KT + k0, KT, st + 16384);
            cpa_tile_dual(B1h + (size_t)col0 * KT + k0, B3h + (size_t)col0 * KT + k0, KT, st + 32768);
            cpa_tile_dual(B1l + (size_t)col0 * KT + k0, B3l + (size_t)col0 * KT + k0, KT, st + 49152);
            CP_COMMIT();
        }
        compute_stage<1>(sb + (s % NSTAGE) * STAGE_BYTES, m0, warpN, lane, acc);
    }

#pragma unroll
    for (int mt = 0; mt < 2; mt++) {
        const int rbase = row0 + m0 + mt * 16 + (lane >> 2);
#pragma unroll
        for (int nt = 0; nt < 4; nt++) {
            const int col = col0 + warpN * 32 + nt * 8 + (lane & 3) * 2;
            float* c1 = acc[mt][nt];
            float* c3 = acc[mt][nt + 4];
            float o00 = silu_f(c1[0]) * c3[0], o01 = silu_f(c1[1]) * c3[1];
            float o10 = silu_f(c1[2]) * c3[2], o11 = silu_f(c1[3]) * c3[3];
            uint32_t h0, l0, h1, l1;
            split2(o00, o01, h0, l0);
            split2(o10, o11, h1, l1);
            *reinterpret_cast<uint32_t*>(Hh + (size_t)rbase * NTOT + col) = h0;
            *reinterpret_cast<uint32_t*>(Hl + (size_t)rbase * NTOT + col) = l0;
            *reinterpret_cast<uint32_t*>(Hh + (size_t)(rbase + 8) * NTOT + col) = h1;
            *reinterpret_cast<uint32_t*>(Hl + (size_t)(rbase + 8) * NTOT + col) = l1;
        }
    }
}

// ---------------- plain GEMM: O(fp32) = A @ W  (MODE 1 fuses routed-expert combine) ----------------
template <int MODE>
__global__ __launch_bounds__(256, 1) void plain_tc(float* __restrict__ Oext) {
    constexpr int KT = (MODE == 0) ? DFF : DFS;
    constexpr int NS = KT / 64;

    const int e = blockIdx.z;
    const __nv_bfloat16 *Ah, *Al, *Bh, *Bl;
    float* O;
    int valid;
    if (MODE == 0) {
        valid = min(g_cnt[e], CAP);
        Ah = g_Hh + (size_t)e * CAP * DFF;  Al = g_Hl + (size_t)e * CAP * DFF;
        Bh = g_w2h + (size_t)e * DM * DFF;  Bl = g_w2l + (size_t)e * DM * DFF;
        O  = g_Y + (size_t)e * CAP * DM;
    } else {
        valid = T_TOK;
        Ah = g_Hsh; Al = g_Hsl;
        Bh = g_ws2h; Bl = g_ws2l;
        O = Oext;
    }
    const int row0 = blockIdx.y * 128;
    if (row0 >= valid) return;
    const int col0 = blockIdx.x * 128;

    extern __shared__ char smem[];
    const uint32_t sb = (smem_u32(smem) + 1023u) & ~1023u;

    const int tid = threadIdx.x, lane = tid & 31, warp = tid >> 5;
    const int warpM = warp & 3, warpN = warp >> 2;
    const int m0 = warpM * 32;

    float acc[2][8][4];
#pragma unroll
    for (int i = 0; i < 2; i++)
#pragma unroll
        for (int j = 0; j < 8; j++)
#pragma unroll
            for (int q = 0; q < 4; q++) acc[i][j][q] = 0.f;

#pragma unroll
    for (int s = 0; s < NSTAGE - 1; s++) {
        const uint32_t st = sb + s * STAGE_BYTES;
        const int k0 = s * 64;
        cpa_tile(Ah + (size_t)row0 * KT + k0, KT, st);
        cpa_tile(Al + (size_t)row0 * KT + k0, KT, st + 16384);
        cpa_tile(Bh + (size_t)col0 * KT + k0, KT, st + 32768);
        cpa_tile(Bl + (size_t)col0 * KT + k0, KT, st + 49152);
        CP_COMMIT();
    }

    for (int s = 0; s < NS; s++) {
        if (s == NS - 1) { CP_WAIT(0); } else { CP_WAIT(1); }
        __syncthreads();
        if (s + NSTAGE - 1 < NS) {
            const int sp = s + NSTAGE - 1;
            const uint32_t st = sb + (sp % NSTAGE) * STAGE_BYTES;
            const int k0 = sp * 64;
            cpa_tile(Ah + (size_t)row0 * KT + k0, KT, st);
            cpa_tile(Al + (size_t)row0 * KT + k0, KT, st + 16384);
            cpa_tile(Bh + (size_t)col0 * KT + k0, KT, st + 32768);
            cpa_tile(Bl + (size_t)col0 * KT + k0, KT, st + 49152);
            CP_COMMIT();
        }
        compute_stage<0>(sb + (s % NSTAGE) * STAGE_BYTES, m0, warpN, lane, acc);
    }

#pragma unroll
    for (int mt = 0; mt < 2; mt++) {
        const int r0 = row0 + m0 + mt * 16 + (lane >> 2);
        const int r1 = r0 + 8;
        int s0a = -1, s1a = -1, s0b = -1, s1b = -1;
        float w0a = 0.f, w1a = 0.f, w0b = 0.f, w1b = 0.f;
        if (MODE == 1) {   // fused combine: rows are token ids
            s0a = g_slot[2 * r0];     s1a = g_slot[2 * r0 + 1];
            w0a = g_wt[2 * r0];       w1a = g_wt[2 * r0 + 1];
            s0b = g_slot[2 * r1];     s1b = g_slot[2 * r1 + 1];
            w0b = g_wt[2 * r1];       w1b = g_wt[2 * r1 + 1];
        }
#pragma unroll
        for (int nt = 0; nt < 8; nt++) {
            const int col = col0 + warpN * 64 + nt * 8 + (lane & 3) * 2;
            float* c = acc[mt][nt];
            float2 v0 = make_float2(c[0], c[1]);
            float2 v1 = make_float2(c[2], c[3]);
            if (MODE == 1) {
                if (s0a >= 0) {
                    float2 y = *reinterpret_cast<const float2*>(&g_Y[(size_t)s0a * DM + col]);
                    v0.x += w0a * y.x; v0.y += w0a * y.y;
                }
                if (s1a >= 0) {
                    float2 y = *reinterpret_cast<const float2*>(&g_Y[(size_t)s1a * DM + col]);
                    v0.x += w1a * y.x; v0.y += w1a * y.y;
                }
                if (s0b >= 0) {
                    float2 y = *reinterpret_cast<const float2*>(&g_Y[(size_t)s0b * DM + col]);
                    v1.x += w0b * y.x; v1.y += w0b * y.y;
                }
                if (s1b >= 0) {
                    float2 y = *reinterpret_cast<const float2*>(&g_Y[(size_t)s1b * DM + col]);
                    v1.x += w1b * y.x; v1.y += w1b * y.y;
                }
            }
            *reinterpret_cast<float2*>(O + (size_t)r0 * DM + col) = v0;
            *reinterpret_cast<float2*>(O + (size_t)r1 * DM + col) = v1;
        }
    }
}

// ---------------- launch ----------------
extern "C" void kernel_launch(void* const* d_in, const int* in_sizes, int n_in,
                              void* d_out, int out_size) {
    const float* hs  = (const float*)d_in[0];
    const float* Wg  = (const float*)d_in[1];
    const float* w1  = (const float*)d_in[2];
    const float* w3  = (const float*)d_in[3];
    const float* w2  = (const float*)d_in[4];
    const float* ws1 = (const float*)d_in[5];
    const float* ws3 = (const float*)d_in[6];
    const float* ws2 = (const float*)d_in[7];
    float* out = (float*)d_out;

    cudaFuncSetAttribute(swiglu_tc<0>, cudaFuncAttributeMaxDynamicSharedMemorySize, SMEM_BYTES);
    cudaFuncSetAttribute(swiglu_tc<1>, cudaFuncAttributeMaxDynamicSharedMemorySize, SMEM_BYTES);
    cudaFuncSetAttribute(plain_tc<0>,  cudaFuncAttributeMaxDynamicSharedMemorySize, SMEM_BYTES);
    cudaFuncSetAttribute(plain_tc<1>,  cudaFuncAttributeMaxDynamicSharedMemorySize, SMEM_BYTES);

    zero_cnt_kernel<<<1, 32>>>();
    wsplit_all<<<27648, dim3(32, 8)>>>(w1, w3, w2, ws1, ws3, ws2);
    router_kernel<<<T_TOK / 8, 256>>>(hs, Wg);

    // expert path
    swiglu_tc<0><<<dim3(DFF / 64, CAP / 128, NE), 256, SMEM_BYTES>>>();
    plain_tc<0><<<dim3(DM / 128, CAP / 128, NE), 256, SMEM_BYTES>>>(nullptr);

    // shared expert path; down-proj writes full d_out and fuses routed combine
    swiglu_tc<1><<<dim3(DFS / 64, T_TOK / 128, 1), 256, SMEM_BYTES>>>();
    plain_tc<1><<<dim3(DM / 128, T_TOK / 128, 1), 256, SMEM_BYTES>>>(out);
}